// round 10
// baseline (speedup 1.0000x reference)
#include <cuda_runtime.h>

// Inverse 2D Haar DWT, collapsed to the per-2x2-block butterfly:
//   out[2i  ,2j  ] = 0.5*(LL + LH + HL + HH)
//   out[2i  ,2j+1] = 0.5*(LL - LH + HL - HH)
//   out[2i+1,2j  ] = 0.5*(LL + LH - HL - HH)
//   out[2i+1,2j+1] = 0.5*(LL - LH - HL + HH)
//
// Shapes: in (32,128,56,56) f32 x4 -> out (32,128,112,112) f32
//
// Converged access pattern (unchanged from the 63.55us best):
//  - one input column-pair per thread; float2 streaming loads, perfectly
//    linear across the grid (in_off = 2*idx)
//  - two float4 streaming stores per thread, contiguous across the warp
//    per output row (512B/warp/instruction, no split sectors)
//  - exact grid, no tail predicate; single %28 for index math
//
// R10 probe: 128-thread blocks (50,176 one-shot blocks = 128 x 392 exact).
// Byte-identical DRAM pattern (indexing is a pure function of global idx);
// only CTA granularity changes — finer load-burst interleaving at the
// L1tex queue, smaller per-CTA tail. Last unexplored axis.

#define W_OUT  112
#define WPAIRS 28

__global__ __launch_bounds__(128)
void idwt_haar_kernel(const float* __restrict__ LL,
                      const float* __restrict__ LH,
                      const float* __restrict__ HL,
                      const float* __restrict__ HH,
                      float* __restrict__ out)
{
    unsigned idx = blockIdx.x * blockDim.x + threadIdx.x;   // exact grid, no tail

    unsigned jj      = idx % WPAIRS;
    long     in_off  = 2L * idx;
    long     out_off = 8L * idx - 4L * jj;

    float2 ll = __ldcs(reinterpret_cast<const float2*>(LL + in_off));
    float2 lh = __ldcs(reinterpret_cast<const float2*>(LH + in_off));
    float2 hl = __ldcs(reinterpret_cast<const float2*>(HL + in_off));
    float2 hh = __ldcs(reinterpret_cast<const float2*>(HH + in_off));

    float p0 = ll.x + hl.x, m0 = ll.x - hl.x;
    float q0 = lh.x + hh.x, r0 = lh.x - hh.x;
    float p1 = ll.y + hl.y, m1 = ll.y - hl.y;
    float q1 = lh.y + hh.y, r1 = lh.y - hh.y;

    float4 row_even = make_float4(0.5f * (p0 + q0), 0.5f * (p0 - q0),
                                  0.5f * (p1 + q1), 0.5f * (p1 - q1));
    float4 row_odd  = make_float4(0.5f * (m0 + r0), 0.5f * (m0 - r0),
                                  0.5f * (m1 + r1), 0.5f * (m1 - r1));

    __stcs(reinterpret_cast<float4*>(out + out_off),         row_even);
    __stcs(reinterpret_cast<float4*>(out + out_off + W_OUT), row_odd);
}

extern "C" void kernel_launch(void* const* d_in, const int* in_sizes, int n_in,
                              void* d_out, int out_size)
{
    const float* LL = (const float*)d_in[0];
    const float* LH = (const float*)d_in[1];
    const float* HL = (const float*)d_in[2];
    const float* HH = (const float*)d_in[3];
    float* out = (float*)d_out;

    int total   = in_sizes[0] / 2;          // 6,422,528 = 50176 * 128 exactly
    int threads = 128;
    int blocks  = total / threads;          // exact division, no remainder

    idwt_haar_kernel<<<blocks, threads>>>(LL, LH, HL, HH, out);
}

// round 11
// speedup vs baseline: 1.0020x; 1.0020x over previous
#include <cuda_runtime.h>

// Inverse 2D Haar DWT, collapsed to the per-2x2-block butterfly:
//   out[2i  ,2j  ] = 0.5*(LL + LH + HL + HH)
//   out[2i  ,2j+1] = 0.5*(LL - LH + HL - HH)
//   out[2i+1,2j  ] = 0.5*(LL + LH - HL - HH)
//   out[2i+1,2j+1] = 0.5*(LL - LH - HL + HH)
//
// Shapes: in (32,128,56,56) f32 x4 -> out (32,128,112,112) f32
//
// Converged access pattern (identical DRAM footprint since R1):
//  - one input column-pair per thread; float2 streaming loads, perfectly
//    linear across the grid (in_off = 2*idx)
//  - two float4 streaming stores per thread, contiguous across the warp
//    per output row (512B/warp/instruction, no split sectors)
//  - exact grid, no tail predicate; single %28 for index math
//
// Block-shape ladder: 256thr -> ncu 57.15-57.66us; 128thr -> 56.80us
// (best; finer CTA granularity = shallower cross-CTA L1tex queue tails).
// R11 probe: 64-thread blocks (100,352 one-shot CTAs, 2 warps each) —
// the last step along the only axis that measurably improved counters.

#define W_OUT  112
#define WPAIRS 28

__global__ __launch_bounds__(64)
void idwt_haar_kernel(const float* __restrict__ LL,
                      const float* __restrict__ LH,
                      const float* __restrict__ HL,
                      const float* __restrict__ HH,
                      float* __restrict__ out)
{
    unsigned idx = blockIdx.x * blockDim.x + threadIdx.x;   // exact grid, no tail

    unsigned jj      = idx % WPAIRS;
    long     in_off  = 2L * idx;
    long     out_off = 8L * idx - 4L * jj;

    float2 ll = __ldcs(reinterpret_cast<const float2*>(LL + in_off));
    float2 lh = __ldcs(reinterpret_cast<const float2*>(LH + in_off));
    float2 hl = __ldcs(reinterpret_cast<const float2*>(HL + in_off));
    float2 hh = __ldcs(reinterpret_cast<const float2*>(HH + in_off));

    float p0 = ll.x + hl.x, m0 = ll.x - hl.x;
    float q0 = lh.x + hh.x, r0 = lh.x - hh.x;
    float p1 = ll.y + hl.y, m1 = ll.y - hl.y;
    float q1 = lh.y + hh.y, r1 = lh.y - hh.y;

    float4 row_even = make_float4(0.5f * (p0 + q0), 0.5f * (p0 - q0),
                                  0.5f * (p1 + q1), 0.5f * (p1 - q1));
    float4 row_odd  = make_float4(0.5f * (m0 + r0), 0.5f * (m0 - r0),
                                  0.5f * (m1 + r1), 0.5f * (m1 - r1));

    __stcs(reinterpret_cast<float4*>(out + out_off),         row_even);
    __stcs(reinterpret_cast<float4*>(out + out_off + W_OUT), row_odd);
}

extern "C" void kernel_launch(void* const* d_in, const int* in_sizes, int n_in,
                              void* d_out, int out_size)
{
    const float* LL = (const float*)d_in[0];
    const float* LH = (const float*)d_in[1];
    const float* HL = (const float*)d_in[2];
    const float* HH = (const float*)d_in[3];
    float* out = (float*)d_out;

    int total   = in_sizes[0] / 2;          // 6,422,528 = 100352 * 64 exactly
    int threads = 64;
    int blocks  = total / threads;          // exact division, no remainder

    idwt_haar_kernel<<<blocks, threads>>>(LL, LH, HL, HH, out);
}